// round 15
// baseline (speedup 1.0000x reference)
#include <cuda_runtime.h>
#include <cstdint>

// GraphAttention: nf=x@W ; g=head-sum(nf) ; s1/s2=g.a1/a2 ; lrelu+mask+softmax(j) ; agg.
// Quad-local (128-thr) GEMM 32rx32c per warp (1-wf W reads), skewed banks,
// per-quad XA regions (fixes cross-quad skew-spill race), no block-wide syncs in loop.
#define NN      16
#define FINN    64
#define COLS    128
#define ROWS_PP 64
#define NPASS   8192
#define GRID    2048
#define THREADS 256

// smem offsets (floats)
#define OFF_W   0            // [64 k][128 c]
#define OFF_NF  8192         // [64 r][132] + (row>>3)*4 skew (no cross-row data overlap)
#define OFF_XA  16704        // per-quad regions: q*2192 ; x [lr][68]+skew / attn [lr*68+h*16+j]
#define XAQ     2192         // 32*68 + 16 spill pad
#define OFF_S1  21120        // [64][4]
#define OFF_S2  21376
#define OFF_A1  21632        // [4][36]
#define OFF_A2  21776
#define SMEM_FLOATS 21920
#define SMEM_BYTES  (SMEM_FLOATS * 4)   // 87680 B -> 2 blocks/SM

typedef unsigned long long ull;

__device__ __forceinline__ ull pack2(float lo, float hi) {
    ull o; asm("mov.b64 %0, {%1, %2};" : "=l"(o) : "f"(lo), "f"(hi)); return o;
}
__device__ __forceinline__ void fma2(ull& d, ull a, ull b, ull c) {
    asm("fma.rn.f32x2 %0, %1, %2, %3;" : "=l"(d) : "l"(a), "l"(b), "l"(c));
}

__global__ __launch_bounds__(THREADS, 2)
void gat_kernel(const float* __restrict__ x,
                const float* __restrict__ W,
                const float* __restrict__ attv,
                const float* __restrict__ adj,
                float* __restrict__ out)
{
    extern __shared__ float smf[];
    const int t = threadIdx.x;
    const int warp = t >> 5;
    const int lane = t & 31;
    const int q    = warp >> 2;          // quad (0/1): rows 32q..32q+31 (2 graphs)
    const int wq   = warp & 3;           // warp in quad
    const int Q0   = 32 * q;
    const int qt   = t & 127;            // thread in quad
    const int pt   = t & 63;             // thread in pair
    const int pr   = warp >> 1;          // pair index (0..3) = graph slot
    const int bq   = 1 + q;              // quad barrier id
    const int bp   = 3 + pr;             // pair barrier id

    float* xaq = smf + OFF_XA + q * XAQ; // this quad's x/attn region (local rows 0..31)

    // GEMM lane mapping: rh (4 groups of 8 rows), c4g (8 col4 groups)
    const int rh  = lane >> 3;
    const int c4g = lane & 7;
    // agg mapping: warp -> local rows 8wq..8wq+7 ; lane -> c4 over 128 cols ; head = lane>>3
    const int hh  = lane >> 3;

    // ---- one-time setup: W, att vectors, adjacency bitmask ----
    #pragma unroll
    for (int qq = 0; qq < 8; qq++)
        ((float4*)(smf + OFF_W))[t + 256 * qq] = ((const float4*)W)[t + 256 * qq];
    {
        const int h = t >> 6, f2 = t & 63;
        const float v = attv[t];
        if (f2 < 32) smf[OFF_A1 + h * 36 + f2] = v;
        else         smf[OFF_A2 + h * 36 + (f2 - 32)] = v;
    }
    unsigned amask = 0;
    {
        const int i = (qt >> 2) & 15;
        #pragma unroll
        for (int j = 0; j < NN; j++)
            if (adj[i * NN + j] != 0.f) amask |= (1u << j);
    }
    __syncthreads();

    for (int tp = blockIdx.x; tp < NPASS; tp += GRID) {
        const size_t row0 = (size_t)tp * ROWS_PP;

        // ---- stage x: pair loads its graph (16x64) -> quad-local pitch-68 + skew ----
        {
            const int R0l = 16 * (pr & 1);                 // local row base in quad region
            const float4* gx = (const float4*)(x + (row0 + 16 * pr) * FINN);
            #pragma unroll
            for (int qq = 0; qq < 4; qq++) {
                const int idx = pt + 64 * qq;
                const int lr = R0l + (idx >> 4);
                const float4 v = gx[idx];
                *(float4*)(xaq + lr * 68 + (lr >> 3) * 4 + 4 * (idx & 15)) = v;
            }
        }
        asm volatile("bar.sync %0, 128;" :: "r"(bq) : "memory");

        // ---- GEMM: warp = 32 rows x 32 cols; lane = 8 rows x 4 cols ----
        {
            const float* xrow = xaq + (8 * rh) * 68 + rh * 4;   // local rows 8rh..8rh+7
            const float* wcol = smf + OFF_W + 32 * wq + c4g * 4;
            ull acc[8][2];
            #pragma unroll
            for (int r = 0; r < 8; r++) { acc[r][0] = 0; acc[r][1] = 0; }
            #pragma unroll
            for (int k4 = 0; k4 < 16; k4++) {
                float4 xv[8];
                #pragma unroll
                for (int r = 0; r < 8; r++)
                    xv[r] = *(const float4*)(xrow + r * 68 + k4 * 4);
                #pragma unroll
                for (int kk = 0; kk < 4; kk++) {
                    const ulonglong2 wv = *(const ulonglong2*)(wcol + (k4 * 4 + kk) * COLS);
                    #pragma unroll
                    for (int r = 0; r < 8; r++) {
                        const float xs = (kk == 0) ? xv[r].x : (kk == 1) ? xv[r].y
                                       : (kk == 2) ? xv[r].z : xv[r].w;
                        const ull xx = pack2(xs, xs);
                        fma2(acc[r][0], xx, wv.x, acc[r][0]);
                        fma2(acc[r][1], xx, wv.y, acc[r][1]);
                    }
                }
            }
            #pragma unroll
            for (int r = 0; r < 8; r++) {
                const int row = Q0 + 8 * rh + r;                // global row for NF
                ulonglong2 st; st.x = acc[r][0]; st.y = acc[r][1];
                *(ulonglong2*)(smf + OFF_NF + row * 132 + (row >> 3) * 4 + 32 * wq + c4g * 4) = st;
            }
        }
        asm volatile("bar.sync %0, 128;" :: "r"(bq) : "memory");

        // ---- s1/s2: thread -> (row = Q0 + qt>>2, fq = qt&3 -> 8 f's); shfl-reduce over fq ----
        {
            const int row = Q0 + (qt >> 2), fq = qt & 3;
            const int fb = fq * 8;
            const float* nfr = smf + OFF_NF + row * 132 + (row >> 3) * 4 + fb;
            float g[8];
            #pragma unroll
            for (int b4 = 0; b4 < 2; b4++) {
                float4 s = *(const float4*)(nfr + b4 * 4);
                const float4 n1 = *(const float4*)(nfr + 32 + b4 * 4);
                const float4 n2 = *(const float4*)(nfr + 64 + b4 * 4);
                const float4 n3 = *(const float4*)(nfr + 96 + b4 * 4);
                s.x += n1.x + n2.x + n3.x; s.y += n1.y + n2.y + n3.y;
                s.z += n1.z + n2.z + n3.z; s.w += n1.w + n2.w + n3.w;
                g[b4 * 4 + 0] = s.x; g[b4 * 4 + 1] = s.y; g[b4 * 4 + 2] = s.z; g[b4 * 4 + 3] = s.w;
            }
            float p1[4], p2[4];
            #pragma unroll
            for (int h = 0; h < 4; h++) {
                const float4 a1a = *(const float4*)(smf + OFF_A1 + h * 36 + fb);
                const float4 a1b = *(const float4*)(smf + OFF_A1 + h * 36 + fb + 4);
                const float4 a2a = *(const float4*)(smf + OFF_A2 + h * 36 + fb);
                const float4 a2b = *(const float4*)(smf + OFF_A2 + h * 36 + fb + 4);
                p1[h] = g[0] * a1a.x + g[1] * a1a.y + g[2] * a1a.z + g[3] * a1a.w
                      + g[4] * a1b.x + g[5] * a1b.y + g[6] * a1b.z + g[7] * a1b.w;
                p2[h] = g[0] * a2a.x + g[1] * a2a.y + g[2] * a2a.z + g[3] * a2a.w
                      + g[4] * a2b.x + g[5] * a2b.y + g[6] * a2b.z + g[7] * a2b.w;
            }
            #pragma unroll
            for (int h = 0; h < 4; h++) {
                p1[h] += __shfl_xor_sync(0xFFFFFFFF, p1[h], 1);
                p1[h] += __shfl_xor_sync(0xFFFFFFFF, p1[h], 2);
                p2[h] += __shfl_xor_sync(0xFFFFFFFF, p2[h], 1);
                p2[h] += __shfl_xor_sync(0xFFFFFFFF, p2[h], 2);
            }
            if (fq == 0) {
                *(float4*)(smf + OFF_S1 + row * 4) = make_float4(p1[0], p1[1], p1[2], p1[3]);
                *(float4*)(smf + OFF_S2 + row * 4) = make_float4(p2[0], p2[1], p2[2], p2[3]);
            }
        }
        asm volatile("bar.sync %0, 64;" :: "r"(bp) : "memory");

        // ---- softmax: thread -> (lr = qt>>2, h = qt&3); attn -> xaq[lr*68 + h*16 + j] ----
        {
            const int lr = qt >> 2, h = qt & 3;
            const int i = Q0 + lr;
            const int jb = Q0 + (lr & 16);
            const float s1 = smf[OFF_S1 + i * 4 + h];
            float sc[NN];
            float mx = -1e30f;
            #pragma unroll
            for (int j = 0; j < NN; j++) {
                float s = s1 + smf[OFF_S2 + (jb + j) * 4 + h];
                s = (s > 0.f) ? s : 0.2f * s;
                const bool valid = (amask >> j) & 1u;
                sc[j] = valid ? s : -1e30f;
                mx = (valid && s > mx) ? s : mx;
            }
            float sum = 0.f;
            #pragma unroll
            for (int j = 0; j < NN; j++) {
                const float e = (sc[j] > -1e29f) ? __expf(sc[j] - mx) : 0.f;
                sc[j] = e;
                sum += e;
            }
            const float inv = 1.f / sum;
            float* arow = xaq + lr * 68 + h * 16;
            #pragma unroll
            for (int j4 = 0; j4 < 4; j4++)
                *(float4*)(arow + 4 * j4) = make_float4(sc[4 * j4] * inv, sc[4 * j4 + 1] * inv,
                                                        sc[4 * j4 + 2] * inv, sc[4 * j4 + 3] * inv);
        }
        __syncwarp();   // agg warp reads attn rows written by this same warp

        // ---- agg: warp -> local rows 8wq..8wq+7, lane -> c4 over 128 cols; j blocked by 4 ----
        {
            const int lr0 = 8 * wq;                     // local attn row base (warp's rows)
            const int ajb = Q0 + (wq & 2) * 8;          // global nf row base of warp's graph
            ull acc[8][2];
            #pragma unroll
            for (int r = 0; r < 8; r++) { acc[r][0] = 0; acc[r][1] = 0; }
            #pragma unroll
            for (int j4 = 0; j4 < 4; j4++) {
                ull nfv[4][2];
                #pragma unroll
                for (int jj = 0; jj < 4; jj++) {
                    const int row = ajb + 4 * j4 + jj;
                    const ulonglong2 v = *(const ulonglong2*)(smf + OFF_NF + row * 132 + (row >> 3) * 4 + lane * 4);
                    nfv[jj][0] = v.x; nfv[jj][1] = v.y;
                }
                #pragma unroll
                for (int r = 0; r < 8; r++) {
                    const float4 af = *(const float4*)(xaq + (lr0 + r) * 68 + hh * 16 + 4 * j4);
                    ull aa;
                    aa = pack2(af.x, af.x);
                    fma2(acc[r][0], aa, nfv[0][0], acc[r][0]); fma2(acc[r][1], aa, nfv[0][1], acc[r][1]);
                    aa = pack2(af.y, af.y);
                    fma2(acc[r][0], aa, nfv[1][0], acc[r][0]); fma2(acc[r][1], aa, nfv[1][1], acc[r][1]);
                    aa = pack2(af.z, af.z);
                    fma2(acc[r][0], aa, nfv[2][0], acc[r][0]); fma2(acc[r][1], aa, nfv[2][1], acc[r][1]);
                    aa = pack2(af.w, af.w);
                    fma2(acc[r][0], aa, nfv[3][0], acc[r][0]); fma2(acc[r][1], aa, nfv[3][1], acc[r][1]);
                }
            }
            #pragma unroll
            for (int r = 0; r < 8; r++) {
                ulonglong2 st; st.x = acc[r][0]; st.y = acc[r][1];
                *(ulonglong2*)(out + (row0 + Q0 + lr0 + r) * COLS + lane * 4) = st;
            }
        }
        // end of pass: next stage/GEMM overwrite this quad's XA/NF rows (quad-local)
        asm volatile("bar.sync %0, 128;" :: "r"(bq) : "memory");
    }
}

extern "C" void kernel_launch(void* const* d_in, const int* in_sizes, int n_in,
                              void* d_out, int out_size) {
    const float* x    = (const float*)d_in[0];
    const float* W    = (const float*)d_in[1];
    const float* attv = (const float*)d_in[2];
    const float* adj  = (const float*)d_in[3];
    float* out = (float*)d_out;
    (void)in_sizes; (void)n_in; (void)out_size;

    cudaFuncSetAttribute(gat_kernel, cudaFuncAttributeMaxDynamicSharedMemorySize, SMEM_BYTES);
    gat_kernel<<<GRID, THREADS, SMEM_BYTES>>>(x, W, attv, adj, out);
}

// round 16
// speedup vs baseline: 1.3772x; 1.3772x over previous
#include <cuda_runtime.h>
#include <cuda_bf16.h>
#include <cstdint>

// GraphAttention: nf=x@W (split-bf16 HMMA) ; g=head-sum(nf) ; s1/s2 ; lrelu+mask+softmax ; agg.
// R12 pair-local skeleton; GEMM on tensor pipe via mma.sync.m16n8k16.bf16 (3-product split).
#define NN      16
#define FINN    64
#define COLS    128
#define ROWS_PP 64
#define NPASS   8192
#define GRID    2048
#define THREADS 256

// smem offsets (floats)
#define OFF_W   0            // W fragments: [v(2)][kt(4)][nt(16)][lane(32)] ull = 8192 floats
#define OFF_NF  8192         // [64 r][132]
#define OFF_XA  16640        // x [r][68] / attn [i*68 + h*16 + j] (pair-local, time-disjoint)
#define OFF_S1  20992        // [64][4]
#define OFF_S2  21248
#define OFF_A1  21504        // [4][36]
#define OFF_A2  21648
#define SMEM_FLOATS 21792
#define SMEM_BYTES  (SMEM_FLOATS * 4)   // 87168 B -> 2 blocks/SM

typedef unsigned long long ull;

__device__ __forceinline__ ull pack2(float lo, float hi) {
    ull o; asm("mov.b64 %0, {%1, %2};" : "=l"(o) : "f"(lo), "f"(hi)); return o;
}
__device__ __forceinline__ void fma2(ull& d, ull a, ull b, ull c) {
    asm("fma.rn.f32x2 %0, %1, %2, %3;" : "=l"(d) : "l"(a), "l"(b), "l"(c));
}
__device__ __forceinline__ unsigned bfp(float a, float b) {   // {low=bf16(a), high=bf16(b)}
    __nv_bfloat162 h; h.x = __float2bfloat16(a); h.y = __float2bfloat16(b);
    return *reinterpret_cast<unsigned*>(&h);
}
__device__ __forceinline__ float resid(float a) {
    return a - __bfloat162float(__float2bfloat16(a));
}
__device__ __forceinline__ void hmma(float* c, unsigned a0, unsigned a1, unsigned a2, unsigned a3,
                                     unsigned b0, unsigned b1) {
    asm("mma.sync.aligned.m16n8k16.row.col.f32.bf16.bf16.f32 "
        "{%0,%1,%2,%3}, {%4,%5,%6,%7}, {%8,%9}, {%0,%1,%2,%3};"
        : "+f"(c[0]), "+f"(c[1]), "+f"(c[2]), "+f"(c[3])
        : "r"(a0), "r"(a1), "r"(a2), "r"(a3), "r"(b0), "r"(b1));
}

__global__ __launch_bounds__(THREADS, 2)
void gat_kernel(const float* __restrict__ x,
                const float* __restrict__ W,
                const float* __restrict__ attv,
                const float* __restrict__ adj,
                float* __restrict__ out)
{
    extern __shared__ float smf[];
    ull* wf = (ull*)(smf + OFF_W);
    const int t = threadIdx.x;
    const int warp = t >> 5;
    const int lane = t & 31;
    const int pt   = t & 63;             // thread in pair
    const int pr   = warp >> 1;          // pair = graph slot (0..3)
    const int R0   = 16 * pr;            // pair's row base
    const int bid  = pr + 1;             // pair barrier id
    const int CB   = (warp & 1) * 64;    // warp's column half
    const int g8   = lane >> 2;          // mma group id (0..7)
    const int ct2  = (lane & 3) * 2;     // mma in-group column*2
    // agg mapping (R12): warp -> 8 i-rows of its graph; lane -> c4 over 128 cols
    const int ar0  = R0 + 8 * (warp & 1);
    const int hh   = lane >> 3;

    // ---- one-time setup: W fragments (hi/lo), att vectors, adjacency bitmask ----
    #pragma unroll
    for (int e = 0; e < 16; e++) {
        const int ent = e * 256 + t;
        const int ln = ent & 31, nt = (ent >> 5) & 15, kt = (ent >> 9) & 3, v = ent >> 11;
        const int k0 = kt * 16 + (ln & 3) * 2;
        const int n  = nt * 8 + (ln >> 2);
        const float w00 = W[k0 * COLS + n];
        const float w01 = W[(k0 + 1) * COLS + n];
        const float w10 = W[(k0 + 8) * COLS + n];
        const float w11 = W[(k0 + 9) * COLS + n];
        unsigned b0, b1;
        if (v == 0) { b0 = bfp(w00, w01);               b1 = bfp(w10, w11); }
        else        { b0 = bfp(resid(w00), resid(w01)); b1 = bfp(resid(w10), resid(w11)); }
        wf[((v * 4 + kt) * 16 + nt) * 32 + ln] = (ull)b0 | ((ull)b1 << 32);
    }
    {
        const int h = t >> 6, f2 = t & 63;
        const float v = attv[t];
        if (f2 < 32) smf[OFF_A1 + h * 36 + f2] = v;
        else         smf[OFF_A2 + h * 36 + (f2 - 32)] = v;
    }
    unsigned amask = 0;
    {
        const int i = (pt >> 2);
        #pragma unroll
        for (int j = 0; j < NN; j++)
            if (adj[i * NN + j] != 0.f) amask |= (1u << j);
    }
    __syncthreads();

    for (int tp = blockIdx.x; tp < NPASS; tp += GRID) {
        const size_t row0 = (size_t)tp * ROWS_PP;

        // ---- stage x: pair loads its graph (16x64), pitch-68 ----
        {
            const float4* gx = (const float4*)(x + (row0 + R0) * FINN);
            #pragma unroll
            for (int qq = 0; qq < 4; qq++) {
                const int idx = pt + 64 * qq;
                const float4 v = gx[idx];
                *(float4*)(smf + OFF_XA + (R0 + (idx >> 4)) * 68 + 4 * (idx & 15)) = v;
            }
        }
        asm volatile("bar.sync %0, 64;" :: "r"(bid) : "memory");

        // ---- GEMM: warp = graph's 16 rows x 64 cols, mma.sync m16n8k16 bf16 split ----
        {
            float acc[8][4];
            #pragma unroll
            for (int nt8 = 0; nt8 < 8; nt8++) {
                acc[nt8][0] = 0.f; acc[nt8][1] = 0.f; acc[nt8][2] = 0.f; acc[nt8][3] = 0.f;
            }
            const float* xr0 = smf + OFF_XA + (R0 + g8) * 68;
            const float* xr1 = xr0 + 8 * 68;
            const int ntb = (warp & 1) * 8;
            #pragma unroll
            for (int kt = 0; kt < 4; kt++) {
                const int kb = kt * 16 + ct2;
                const float2 v00 = *(const float2*)(xr0 + kb);
                const float2 v10 = *(const float2*)(xr1 + kb);
                const float2 v01 = *(const float2*)(xr0 + kb + 8);
                const float2 v11 = *(const float2*)(xr1 + kb + 8);
                const unsigned ah0 = bfp(v00.x, v00.y), ah1 = bfp(v10.x, v10.y);
                const unsigned ah2 = bfp(v01.x, v01.y), ah3 = bfp(v11.x, v11.y);
                const unsigned al0 = bfp(resid(v00.x), resid(v00.y));
                const unsigned al1 = bfp(resid(v10.x), resid(v10.y));
                const unsigned al2 = bfp(resid(v01.x), resid(v01.y));
                const unsigned al3 = bfp(resid(v11.x), resid(v11.y));
                const ull* whv = wf + ((0 * 4 + kt) * 16 + ntb) * 32 + lane;
                const ull* wlv = wf + ((1 * 4 + kt) * 16 + ntb) * 32 + lane;
                #pragma unroll
                for (int nt8 = 0; nt8 < 8; nt8++) {
                    const ull wh = whv[nt8 * 32];
                    const ull wl = wlv[nt8 * 32];
                    const unsigned wh0 = (unsigned)wh, wh1 = (unsigned)(wh >> 32);
                    const unsigned wl0 = (unsigned)wl, wl1 = (unsigned)(wl >> 32);
                    hmma(acc[nt8], ah0, ah1, ah2, ah3, wh0, wh1);
                    hmma(acc[nt8], al0, al1, al2, al3, wh0, wh1);
                    hmma(acc[nt8], ah0, ah1, ah2, ah3, wl0, wl1);
                }
            }
            // store D -> NF: c0,c1 = (row g8, cols ct2,ct2+1); c2,c3 = row g8+8
            #pragma unroll
            for (int nt8 = 0; nt8 < 8; nt8++) {
                const int col = CB + nt8 * 8 + ct2;
                const int row = R0 + g8;
                float2 lo2; lo2.x = acc[nt8][0]; lo2.y = acc[nt8][1];
                float2 hi2; hi2.x = acc[nt8][2]; hi2.y = acc[nt8][3];
                *(float2*)(smf + OFF_NF + row * 132 + col)       = lo2;
                *(float2*)(smf + OFF_NF + (row + 8) * 132 + col) = hi2;
            }
        }
        asm volatile("bar.sync %0, 64;" :: "r"(bid) : "memory");

        // ---- s1/s2: thread -> (row = R0 + pt>>2, fq = pt&3 -> 8 f's); shfl-reduce over fq ----
        {
            const int row = R0 + (pt >> 2), fq = pt & 3;
            const int fb = fq * 8;
            const float* nfr = smf + OFF_NF + row * 132 + fb;
            float g[8];
            #pragma unroll
            for (int b4 = 0; b4 < 2; b4++) {
                float4 s = *(const float4*)(nfr + b4 * 4);
                const float4 n1 = *(const float4*)(nfr + 32 + b4 * 4);
                const float4 n2 = *(const float4*)(nfr + 64 + b4 * 4);
                const float4 n3 = *(const float4*)(nfr + 96 + b4 * 4);
                s.x += n1.x + n2.x + n3.x; s.y += n1.y + n2.y + n3.y;
                s.z += n1.z + n2.z + n3.z; s.w += n1.w + n2.w + n3.w;
                g[b4 * 4 + 0] = s.x; g[b4 * 4 + 1] = s.y; g[b4 * 4 + 2] = s.z; g[b4 * 4 + 3] = s.w;
            }
            float p1[4], p2[4];
            #pragma unroll
            for (int h = 0; h < 4; h++) {
                const float4 a1a = *(const float4*)(smf + OFF_A1 + h * 36 + fb);
                const float4 a1b = *(const float4*)(smf + OFF_A1 + h * 36 + fb + 4);
                const float4 a2a = *(const float4*)(smf + OFF_A2 + h * 36 + fb);
                const float4 a2b = *(const float4*)(smf + OFF_A2 + h * 36 + fb + 4);
                p1[h] = g[0] * a1a.x + g[1] * a1a.y + g[2] * a1a.z + g[3] * a1a.w
                      + g[4] * a1b.x + g[5] * a1b.y + g[6] * a1b.z + g[7] * a1b.w;
                p2[h] = g[0] * a2a.x + g[1] * a2a.y + g[2] * a2a.z + g[3] * a2a.w
                      + g[4] * a2b.x + g[5] * a2b.y + g[6] * a2b.z + g[7] * a2b.w;
            }
            #pragma unroll
            for (int h = 0; h < 4; h++) {
                p1[h] += __shfl_xor_sync(0xFFFFFFFF, p1[h], 1);
                p1[h] += __shfl_xor_sync(0xFFFFFFFF, p1[h], 2);
                p2[h] += __shfl_xor_sync(0xFFFFFFFF, p2[h], 1);
                p2[h] += __shfl_xor_sync(0xFFFFFFFF, p2[h], 2);
            }
            if (fq == 0) {
                *(float4*)(smf + OFF_S1 + row * 4) = make_float4(p1[0], p1[1], p1[2], p1[3]);
                *(float4*)(smf + OFF_S2 + row * 4) = make_float4(p2[0], p2[1], p2[2], p2[3]);
            }
        }
        asm volatile("bar.sync %0, 64;" :: "r"(bid) : "memory");

        // ---- softmax: thread -> (i = R0 + pt>>2, h = pt&3); attn -> [i*68 + h*16 + j] ----
        {
            const int i = R0 + (pt >> 2), h = pt & 3;
            const float s1 = smf[OFF_S1 + i * 4 + h];
            float sc[NN];
            float mx = -1e30f;
            #pragma unroll
            for (int j = 0; j < NN; j++) {
                float s = s1 + smf[OFF_S2 + (R0 + j) * 4 + h];
                s = (s > 0.f) ? s : 0.2f * s;
                const bool valid = (amask >> j) & 1u;
                sc[j] = valid ? s : -1e30f;
                mx = (valid && s > mx) ? s : mx;
            }
            float sum = 0.f;
            #pragma unroll
            for (int j = 0; j < NN; j++) {
                const float e = (sc[j] > -1e29f) ? __expf(sc[j] - mx) : 0.f;
                sc[j] = e;
                sum += e;
            }
            const float inv = 1.f / sum;
            float* arow = smf + OFF_XA + i * 68 + h * 16;
            #pragma unroll
            for (int j4 = 0; j4 < 4; j4++)
                *(float4*)(arow + 4 * j4) = make_float4(sc[4 * j4] * inv, sc[4 * j4 + 1] * inv,
                                                        sc[4 * j4 + 2] * inv, sc[4 * j4 + 3] * inv);
        }
        __syncwarp();   // agg warp reads attn rows written by this same warp

        // ---- agg: warp -> 8 i-rows, lane -> c4 (4 cols); j register-blocked by 4 ----
        {
            ull acc[8][2];
            #pragma unroll
            for (int r = 0; r < 8; r++) { acc[r][0] = 0; acc[r][1] = 0; }
            #pragma unroll
            for (int j4 = 0; j4 < 4; j4++) {
                ull nfv[4][2];
                #pragma unroll
                for (int jj = 0; jj < 4; jj++) {
                    const ulonglong2 v = *(const ulonglong2*)(smf + OFF_NF + (R0 + 4 * j4 + jj) * 132 + lane * 4);
                    nfv[jj][0] = v.x; nfv[jj][1] = v.y;
                }
                #pragma unroll
                for (int r = 0; r < 8; r++) {
                    const float4 af = *(const float4*)(smf + OFF_XA + (ar0 + r) * 68 + hh * 16 + 4 * j4);
                    ull aa;
                    aa = pack2(af.x, af.x);
                    fma2(acc[r][0], aa, nfv[0][0], acc[r][0]); fma2(acc[r][1], aa, nfv[0][1], acc[r][1]);
                    aa = pack2(af.y, af.y);
                    fma2(acc[r][0], aa, nfv[1][0], acc[r][0]); fma2(acc[r][1], aa, nfv[1][1], acc[r][1]);
                    aa = pack2(af.z, af.z);
                    fma2(acc[r][0], aa, nfv[2][0], acc[r][0]); fma2(acc[r][1], aa, nfv[2][1], acc[r][1]);
                    aa = pack2(af.w, af.w);
                    fma2(acc[r][0], aa, nfv[3][0], acc[r][0]); fma2(acc[r][1], aa, nfv[3][1], acc[r][1]);
                }
            }
            #pragma unroll
            for (int r = 0; r < 8; r++) {
                ulonglong2 st; st.x = acc[r][0]; st.y = acc[r][1];
                *(ulonglong2*)(out + (row0 + ar0 + r) * COLS + lane * 4) = st;
            }
        }
        // end of pass: next stage overwrites x/attn, next GEMM overwrites nf (pair-local)
        asm volatile("bar.sync %0, 64;" :: "r"(bid) : "memory");
    }
}

extern "C" void kernel_launch(void* const* d_in, const int* in_sizes, int n_in,
                              void* d_out, int out_size) {
    const float* x    = (const float*)d_in[0];
    const float* W    = (const float*)d_in[1];
    const float* attv = (const float*)d_in[2];
    const float* adj  = (const float*)d_in[3];
    float* out = (float*)d_out;
    (void)in_sizes; (void)n_in; (void)out_size;

    cudaFuncSetAttribute(gat_kernel, cudaFuncAttributeMaxDynamicSharedMemorySize, SMEM_BYTES);
    gat_kernel<<<GRID, THREADS, SMEM_BYTES>>>(x, W, attv, adj, out);
}

// round 17
// speedup vs baseline: 1.4125x; 1.0257x over previous
#include <cuda_runtime.h>
#include <cuda_bf16.h>
#include <cstdint>

// GraphAttention: nf=x@W (split-bf16 HMMA) ; g=head-sum(nf) ; s1/s2 ; lrelu+mask+softmax ; agg.
// x pre-split to bf16 hi/lo at stage (no cvt in GEMM loop); W frags hi/lo interleaved (1 LDS.128).
#define NN      16
#define FINN    64
#define COLS    128
#define ROWS_PP 64
#define NPASS   8192
#define GRID    2048
#define THREADS 256

// smem offsets (floats)
#define OFF_W   0            // W frags interleaved: [kt(4)][nt(16)][lane(32)] x ulonglong2 = 8192 f
#define OFF_NF  8192         // [64 r][132]
#define OFF_XB  16640        // per-graph 1152: XH [16r][36 uint] | XL +576 | attn alias [lr*68+h*16+j]
#define XBG     1152
#define OFF_S1  21248        // [64][4]
#define OFF_S2  21504
#define OFF_A1  21760        // [4][36]
#define OFF_A2  21904
#define SMEM_FLOATS 22048
#define SMEM_BYTES  (SMEM_FLOATS * 4)   // 88192 B -> 2 blocks/SM

typedef unsigned long long ull;

__device__ __forceinline__ ull pack2(float lo, float hi) {
    ull o; asm("mov.b64 %0, {%1, %2};" : "=l"(o) : "f"(lo), "f"(hi)); return o;
}
__device__ __forceinline__ void fma2(ull& d, ull a, ull b, ull c) {
    asm("fma.rn.f32x2 %0, %1, %2, %3;" : "=l"(d) : "l"(a), "l"(b), "l"(c));
}
__device__ __forceinline__ unsigned bfp(float a, float b) {   // {low=bf16(a), high=bf16(b)}
    __nv_bfloat162 h; h.x = __float2bfloat16(a); h.y = __float2bfloat16(b);
    return *reinterpret_cast<unsigned*>(&h);
}
__device__ __forceinline__ float resid(float a) {
    return a - __bfloat162float(__float2bfloat16(a));
}
__device__ __forceinline__ void hmma(float* c, unsigned a0, unsigned a1, unsigned a2, unsigned a3,
                                     unsigned b0, unsigned b1) {
    asm("mma.sync.aligned.m16n8k16.row.col.f32.bf16.bf16.f32 "
        "{%0,%1,%2,%3}, {%4,%5,%6,%7}, {%8,%9}, {%0,%1,%2,%3};"
        : "+f"(c[0]), "+f"(c[1]), "+f"(c[2]), "+f"(c[3])
        : "r"(a0), "r"(a1), "r"(a2), "r"(a3), "r"(b0), "r"(b1));
}

__global__ __launch_bounds__(THREADS, 2)
void gat_kernel(const float* __restrict__ x,
                const float* __restrict__ W,
                const float* __restrict__ attv,
                const float* __restrict__ adj,
                float* __restrict__ out)
{
    extern __shared__ float smf[];
    ulonglong2* wc = (ulonglong2*)(smf + OFF_W);
    const int t = threadIdx.x;
    const int warp = t >> 5;
    const int lane = t & 31;
    const int pt   = t & 63;             // thread in pair
    const int pr   = warp >> 1;          // pair = graph slot (0..3)
    const int R0   = 16 * pr;            // pair's row base (NF rows)
    const int bid  = pr + 1;             // pair barrier id
    const int CB   = (warp & 1) * 64;    // warp's column half
    const int g8   = lane >> 2;          // mma group id (0..7)
    const int m4   = lane & 3;           // k-pair selector; ct2 = 2*m4
    const int ar0l = 8 * (warp & 1);     // agg local row base
    const int hh   = lane >> 3;

    float* xbg = smf + OFF_XB + pr * XBG;          // this graph's XH/XL/attn region
    unsigned* xh = (unsigned*)xbg;
    unsigned* xl = (unsigned*)(xbg + 576);

    // ---- one-time setup: W fragments hi/lo interleaved, att vectors, adjacency mask ----
    #pragma unroll
    for (int e = 0; e < 8; e++) {
        const int ent = e * 256 + t;                  // 2048 entries
        const int ln = ent & 31, nt = (ent >> 5) & 15, kt = ent >> 9;
        const int k0 = kt * 16 + (ln & 3) * 2;
        const int n  = nt * 8 + (ln >> 2);
        const float w00 = W[k0 * COLS + n];
        const float w01 = W[(k0 + 1) * COLS + n];
        const float w10 = W[(k0 + 8) * COLS + n];
        const float w11 = W[(k0 + 9) * COLS + n];
        ulonglong2 ww;
        ww.x = (ull)bfp(w00, w01) | ((ull)bfp(w10, w11) << 32);
        ww.y = (ull)bfp(resid(w00), resid(w01)) | ((ull)bfp(resid(w10), resid(w11)) << 32);
        wc[(kt * 16 + nt) * 32 + ln] = ww;
    }
    {
        const int h = t >> 6, f2 = t & 63;
        const float v = attv[t];
        if (f2 < 32) smf[OFF_A1 + h * 36 + f2] = v;
        else         smf[OFF_A2 + h * 36 + (f2 - 32)] = v;
    }
    unsigned amask = 0;
    {
        const int i = (pt >> 2);
        #pragma unroll
        for (int j = 0; j < NN; j++)
            if (adj[i * NN + j] != 0.f) amask |= (1u << j);
    }
    __syncthreads();

    for (int tp = blockIdx.x; tp < NPASS; tp += GRID) {
        const size_t row0 = (size_t)tp * ROWS_PP;

        // ---- stage x: pair loads its graph (16x64), splits to bf16 hi/lo k-pairs ----
        {
            const float4* gx = (const float4*)(x + (row0 + R0) * FINN);
            #pragma unroll
            for (int qq = 0; qq < 4; qq++) {
                const int idx = pt + 64 * qq;
                const int lr = idx >> 4, seg = idx & 15;
                const float4 v = gx[idx];
                uint2 hv, lv;
                hv.x = bfp(v.x, v.y); hv.y = bfp(v.z, v.w);
                lv.x = bfp(resid(v.x), resid(v.y)); lv.y = bfp(resid(v.z), resid(v.w));
                *(uint2*)(xh + lr * 36 + 2 * seg) = hv;
                *(uint2*)(xl + lr * 36 + 2 * seg) = lv;
            }
        }
        asm volatile("bar.sync %0, 64;" :: "r"(bid) : "memory");

        // ---- GEMM: warp = 16 rows x 64 cols; A-frags direct from XH/XL, 3-product split ----
        {
            float acc[8][4];
            #pragma unroll
            for (int n8 = 0; n8 < 8; n8++) {
                acc[n8][0] = 0.f; acc[n8][1] = 0.f; acc[n8][2] = 0.f; acc[n8][3] = 0.f;
            }
            const int ntb = (warp & 1) * 8;
            #pragma unroll
            for (int kt = 0; kt < 4; kt++) {
                const int o = kt * 8 + m4;
                const unsigned ah0 = xh[g8 * 36 + o];
                const unsigned ah1 = xh[(g8 + 8) * 36 + o];
                const unsigned ah2 = xh[g8 * 36 + o + 4];
                const unsigned ah3 = xh[(g8 + 8) * 36 + o + 4];
                const unsigned al0 = xl[g8 * 36 + o];
                const unsigned al1 = xl[(g8 + 8) * 36 + o];
                const unsigned al2 = xl[g8 * 36 + o + 4];
                const unsigned al3 = xl[(g8 + 8) * 36 + o + 4];
                const ulonglong2* wk = wc + (kt * 16 + ntb) * 32 + lane;
                #pragma unroll
                for (int n8 = 0; n8 < 8; n8++) {
                    const ulonglong2 ww = wk[n8 * 32];
                    const unsigned wh0 = (unsigned)ww.x, wh1 = (unsigned)(ww.x >> 32);
                    const unsigned wl0 = (unsigned)ww.y, wl1 = (unsigned)(ww.y >> 32);
                    hmma(acc[n8], ah0, ah1, ah2, ah3, wh0, wh1);
                    hmma(acc[n8], al0, al1, al2, al3, wh0, wh1);
                    hmma(acc[n8], ah0, ah1, ah2, ah3, wl0, wl1);
                }
            }
            #pragma unroll
            for (int n8 = 0; n8 < 8; n8++) {
                const int col = CB + n8 * 8 + 2 * m4;
                const int row = R0 + g8;
                float2 lo2; lo2.x = acc[n8][0]; lo2.y = acc[n8][1];
                float2 hi2; hi2.x = acc[n8][2]; hi2.y = acc[n8][3];
                *(float2*)(smf + OFF_NF + row * 132 + col)       = lo2;
                *(float2*)(smf + OFF_NF + (row + 8) * 132 + col) = hi2;
            }
        }
        asm volatile("bar.sync %0, 64;" :: "r"(bid) : "memory");

        // ---- s1/s2: thread -> (row = R0 + pt>>2, fq = pt&3 -> 8 f's); shfl-reduce over fq ----
        {
            const int row = R0 + (pt >> 2), fq = pt & 3;
            const int fb = fq * 8;
            const float* nfr = smf + OFF_NF + row * 132 + fb;
            float g[8];
            #pragma unroll
            for (int b4 = 0; b4 < 2; b4++) {
                float4 s = *(const float4*)(nfr + b4 * 4);
                const float4 n1 = *(const float4*)(nfr + 32 + b4 * 4);
                const float4 n2 = *(const float4*)(nfr + 64 + b4 * 4);
                const float4 n3 = *(const float4*)(nfr + 96 + b4 * 4);
                s.x += n1.x + n2.x + n3.x; s.y += n1.y + n2.y + n3.y;
                s.z += n1.z + n2.z + n3.z; s.w += n1.w + n2.w + n3.w;
                g[b4 * 4 + 0] = s.x; g[b4 * 4 + 1] = s.y; g[b4 * 4 + 2] = s.z; g[b4 * 4 + 3] = s.w;
            }
            float p1[4], p2[4];
            #pragma unroll
            for (int h = 0; h < 4; h++) {
                const float4 a1a = *(const float4*)(smf + OFF_A1 + h * 36 + fb);
                const float4 a1b = *(const float4*)(smf + OFF_A1 + h * 36 + fb + 4);
                const float4 a2a = *(const float4*)(smf + OFF_A2 + h * 36 + fb);
                const float4 a2b = *(const float4*)(smf + OFF_A2 + h * 36 + fb + 4);
                p1[h] = g[0] * a1a.x + g[1] * a1a.y + g[2] * a1a.z + g[3] * a1a.w
                      + g[4] * a1b.x + g[5] * a1b.y + g[6] * a1b.z + g[7] * a1b.w;
                p2[h] = g[0] * a2a.x + g[1] * a2a.y + g[2] * a2a.z + g[3] * a2a.w
                      + g[4] * a2b.x + g[5] * a2b.y + g[6] * a2b.z + g[7] * a2b.w;
            }
            #pragma unroll
            for (int h = 0; h < 4; h++) {
                p1[h] += __shfl_xor_sync(0xFFFFFFFF, p1[h], 1);
                p1[h] += __shfl_xor_sync(0xFFFFFFFF, p1[h], 2);
                p2[h] += __shfl_xor_sync(0xFFFFFFFF, p2[h], 1);
                p2[h] += __shfl_xor_sync(0xFFFFFFFF, p2[h], 2);
            }
            if (fq == 0) {
                *(float4*)(smf + OFF_S1 + row * 4) = make_float4(p1[0], p1[1], p1[2], p1[3]);
                *(float4*)(smf + OFF_S2 + row * 4) = make_float4(p2[0], p2[1], p2[2], p2[3]);
            }
        }
        asm volatile("bar.sync %0, 64;" :: "r"(bid) : "memory");

        // ---- softmax: thread -> (lr = pt>>2, h = pt&3); attn -> xbg[lr*68 + h*16 + j] ----
        {
            const int lr = pt >> 2, h = pt & 3;
            const int i = R0 + lr;
            const float s1 = smf[OFF_S1 + i * 4 + h];
            float sc[NN];
            float mx = -1e30f;
            #pragma unroll
            for (int j = 0; j < NN; j++) {
                float s = s1 + smf[OFF_S2 + (R0 + j) * 4 + h];
                s = (s > 0.f) ? s : 0.2f * s;
                const bool valid = (amask >> j) & 1u;
                sc[j] = valid ? s : -1e30f;
                mx = (valid && s > mx) ? s : mx;
            }
            float sum = 0.f;
            #pragma unroll
            for (int j = 0; j < NN; j++) {
                const float e = (sc[j] > -1e29f) ? __expf(sc[j] - mx) : 0.f;
                sc[j] = e;
                sum += e;
            }
            const float inv = 1.f / sum;
            float* arow = xbg + lr * 68 + h * 16;
            #pragma unroll
            for (int j4 = 0; j4 < 4; j4++)
                *(float4*)(arow + 4 * j4) = make_float4(sc[4 * j4] * inv, sc[4 * j4 + 1] * inv,
                                                        sc[4 * j4 + 2] * inv, sc[4 * j4 + 3] * inv);
        }
        __syncwarp();   // agg warp reads attn rows written by this same warp

        // ---- agg: warp -> 8 i-rows, lane -> c4 (4 cols); j register-blocked by 4 ----
        {
            ull acc[8][2];
            #pragma unroll
            for (int r = 0; r < 8; r++) { acc[r][0] = 0; acc[r][1] = 0; }
            #pragma unroll
            for (int j4 = 0; j4 < 4; j4++) {
                ull nfv[4][2];
                #pragma unroll
                for (int jj = 0; jj < 4; jj++) {
                    const ulonglong2 v = *(const ulonglong2*)(smf + OFF_NF + (R0 + 4 * j4 + jj) * 132 + lane * 4);
                    nfv[jj][0] = v.x; nfv[jj][1] = v.y;
                }
                #pragma unroll
                for (int r = 0; r < 8; r++) {
                    const float4 af = *(const float4*)(xbg + (ar0l + r) * 68 + hh * 16 + 4 * j4);
                    ull aa;
                    aa = pack2(af.x, af.x);
                    fma2(acc[r][0], aa, nfv[0][0], acc[r][0]); fma2(acc[r][1], aa, nfv[0][1], acc[r][1]);
                    aa = pack2(af.y, af.y);
                    fma2(acc[r][0], aa, nfv[1][0], acc[r][0]); fma2(acc[r][1], aa, nfv[1][1], acc[r][1]);
                    aa = pack2(af.z, af.z);
                    fma2(acc[r][0], aa, nfv[2][0], acc[r][0]); fma2(acc[r][1], aa, nfv[2][1], acc[r][1]);
                    aa = pack2(af.w, af.w);
                    fma2(acc[r][0], aa, nfv[3][0], acc[r][0]); fma2(acc[r][1], aa, nfv[3][1], acc[r][1]);
                }
            }
            #pragma unroll
            for (int r = 0; r < 8; r++) {
                ulonglong2 st; st.x = acc[r][0]; st.y = acc[r][1];
                *(ulonglong2*)(out + (row0 + R0 + ar0l + r) * COLS + lane * 4) = st;
            }
        }
        // end of pass: next stage overwrites XH/XL/attn, next GEMM overwrites NF (pair-local)
        asm volatile("bar.sync %0, 64;" :: "r"(bid) : "memory");
    }
}

extern "C" void kernel_launch(void* const* d_in, const int* in_sizes, int n_in,
                              void* d_out, int out_size) {
    const float* x    = (const float*)d_in[0];
    const float* W    = (const float*)d_in[1];
    const float* attv = (const float*)d_in[2];
    const float* adj  = (const float*)d_in[3];
    float* out = (float*)d_out;
    (void)in_sizes; (void)n_in; (void)out_size;

    cudaFuncSetAttribute(gat_kernel, cudaFuncAttributeMaxDynamicSharedMemorySize, SMEM_BYTES);
    gat_kernel<<<GRID, THREADS, SMEM_BYTES>>>(x, W, attv, adj, out);
}